// round 2
// baseline (speedup 1.0000x reference)
#include <cuda_runtime.h>
#include <math.h>

// ---------------- problem dims ----------------
#define SS    128
#define BB    64
#define EE    512
#define HH    256
#define DHH   512
#define G4H   1024
#define GD    2048
#define LDWD  2052
#define LMAXX 4
#define CC    9

#define NBE   32      // encoder persistent blocks (all co-resident)
#define NBD   128     // decoder persistent blocks (all co-resident)

// ---------------- scratch (static device memory) ----------------
__device__ float g_x   [SS*BB*EE];
__device__ float g_gxf [SS*BB*G4H];
__device__ float g_gxb [SS*BB*G4H];
__device__ float g_h   [SS*BB*DHH];
__device__ float g_hx  [SS*BB*(DHH+EE)];
__device__ float g_wh  [SS*BB*DHH];
__device__ float g_preS[SS*BB*GD];
__device__ float g_pre0[SS*BB*GD];
__device__ float g_pre1[SS*BB*GD];
__device__ float g_dout[LMAXX*SS*BB*DHH];
__device__ float g_henc[2*BB*HH];
__device__ float g_cenc[2*BB*HH];
__device__ float g_egate[2*BB*G4H];
__device__ float g_hd  [BB*DHH];
__device__ float g_cd  [BB*DHH];
__device__ float g_ctx [BB*DHH];
__device__ float g_gpart[6*BB*GD];     // split-K partials (4 ctx-part + 2 hd-part)
__device__ float g_bf[G4H];
__device__ float g_bb[G4H];
__device__ float g_bd[GD];
__device__ float g_Wcat[GD*1024];      // [Wih_d[:, :512] | Whh_d], row-major [2048][1024]
__device__ float g_ohc[LMAXX*GD];

// grid barrier state (zero-initialized)
__device__ unsigned g_barCount;
__device__ unsigned g_barGen;

__device__ __forceinline__ float sigf(float x) { return 1.0f / (1.0f + expf(-x)); }

// software grid barrier: all nb blocks must call; blocks co-resident by construction
__device__ __forceinline__ void gsync(unsigned nb) {
    __syncthreads();
    if (threadIdx.x == 0) {
        unsigned gen = g_barGen;
        __threadfence();
        if (atomicAdd(&g_barCount, 1) == nb - 1) {
            g_barCount = 0;
            __threadfence();
            atomicAdd(&g_barGen, 1);
        } else {
            while (atomicAdd(&g_barGen, 0) == gen) {}
            __threadfence();
        }
    }
    __syncthreads();
}

// ---------------- small prep kernels ----------------
__global__ void k_bias_pack(const float* bih_f, const float* bhh_f,
                            const float* bih_b, const float* bhh_b,
                            const float* bih_d, const float* bhh_d) {
    int i = blockIdx.x * 256 + threadIdx.x;
    if (i < G4H) {
        g_bf[i] = bih_f[i] + bhh_f[i];
        g_bb[i] = bih_b[i] + bhh_b[i];
    }
    if (i < GD) g_bd[i] = bih_d[i] + bhh_d[i];
}

__global__ void k_wcat(const float* Wih_d, const float* Whh_d) {
    int idx = blockIdx.x * 256 + threadIdx.x;
    if (idx < GD * 1024) {
        int j = idx >> 10, k = idx & 1023;
        g_Wcat[idx] = (k < 512) ? Wih_d[(size_t)j * LDWD + k]
                                : Whh_d[(size_t)j * DHH + (k - 512)];
    } else {
        int r = idx - GD * 1024;
        if (r < LMAXX * GD) {
            int lvl = r >> 11, n = r & 2047;
            g_ohc[lvl * GD + n] = Wih_d[(size_t)n * LDWD + GD + lvl];
        }
    }
}

__global__ void k_zero() {
    int i = blockIdx.x * 256 + threadIdx.x;
    if (i < 2 * BB * HH) { g_henc[i] = 0.f; g_cenc[i] = 0.f; }
    if (i < BB * DHH)    { g_hd[i] = 0.f;   g_cd[i] = 0.f; }
}

__global__ void k_embed(const int* seqs, const float* emb) {
    int m = blockIdx.x;            // m = s*64 + b
    int s0 = m >> 6, b = m & 63;
    int row = seqs[b * SS + s0];
    const float4* src = (const float4*)(emb + (size_t)row * EE);
    float4* dst = (float4*)(g_x + (size_t)m * EE);
    dst[threadIdx.x] = src[threadIdx.x];
}

__global__ void k_hx() {
    int idx = blockIdx.x * 256 + threadIdx.x;
    int m = idx >> 10, k = idx & 1023;
    g_hx[idx] = (k < 512) ? g_h[(size_t)m * DHH + k] : g_x[(size_t)m * EE + (k - 512)];
}

// ---------------- shared fp32 GEMM core: 64x64 tile, C = A[M,K] * W[N,K]^T ----------------
__device__ __forceinline__ void gemm64_core(const float* __restrict__ A, int lda,
                                            const float* __restrict__ W, int ldw,
                                            int K, int m0, int n0, float acc[4][4]) {
    __shared__ __align__(16) float As[64][20];
    __shared__ __align__(16) float Ws[64][20];
    int tid = threadIdx.x;
    int tm = (tid >> 4) << 2;
    int tn = (tid & 15) << 2;
    for (int k0 = 0; k0 < K; k0 += 16) {
        #pragma unroll
        for (int i = tid; i < 1024; i += 256) {
            int k = i & 15, r = i >> 4;
            As[r][k] = A[(size_t)(m0 + r) * lda + k0 + k];
            Ws[r][k] = W[(size_t)(n0 + r) * ldw + k0 + k];
        }
        __syncthreads();
        #pragma unroll
        for (int kq = 0; kq < 16; kq += 4) {
            float4 a4[4], w4[4];
            #pragma unroll
            for (int i = 0; i < 4; i++) a4[i] = *(const float4*)&As[tm + i][kq];
            #pragma unroll
            for (int j = 0; j < 4; j++) w4[j] = *(const float4*)&Ws[tn + j][kq];
            #pragma unroll
            for (int i = 0; i < 4; i++)
                #pragma unroll
                for (int j = 0; j < 4; j++)
                    acc[i][j] += a4[i].x * w4[j].x + a4[i].y * w4[j].y
                               + a4[i].z * w4[j].z + a4[i].w * w4[j].w;
        }
        __syncthreads();
    }
}

// generic: C[M,N] = A*W^T (+add) (+bias).  grid=(M/64, N/64), 256 threads
__global__ void gemm_nt(const float* __restrict__ A, int lda,
                        const float* __restrict__ W, int ldw,
                        float* __restrict__ C, int N, int K,
                        const float* __restrict__ add, const float* __restrict__ bias) {
    int m0 = blockIdx.x * 64, n0 = blockIdx.y * 64;
    float acc[4][4] = {};
    gemm64_core(A, lda, W, ldw, K, m0, n0, acc);
    int tid = threadIdx.x;
    int tm = (tid >> 4) << 2, tn = (tid & 15) << 2;
    #pragma unroll
    for (int i = 0; i < 4; i++)
        #pragma unroll
        for (int j = 0; j < 4; j++) {
            size_t m = m0 + tm + i, n = n0 + tn + j;
            float v = acc[i][j];
            if (add)  v += add[m * N + n];
            if (bias) v += bias[n];
            C[m * N + n] = v;
        }
}

// ---------------- persistent encoder: all 128 steps, both directions ----------------
__global__ void __launch_bounds__(256, 1) enc_persist(const float* __restrict__ Whh_f,
                                                      const float* __restrict__ Whh_b) {
    int blk = blockIdx.x, tid = threadIdx.x;
    int dir = blk >> 4;
    int n0 = (blk & 15) * 64;
    const float* W = dir ? Whh_b : Whh_f;
    int tm = (tid >> 4) << 2, tn = (tid & 15) << 2;
    for (int t = 0; t < SS; t++) {
        const float* add = dir ? (g_gxb + (size_t)(SS - 1 - t) * BB * G4H)
                               : (g_gxf + (size_t)t * BB * G4H);
        float acc[4][4] = {};
        gemm64_core(g_henc + dir * BB * HH, HH, W, HH, HH, 0, n0, acc);
        float* C = g_egate + (size_t)dir * BB * G4H;
        #pragma unroll
        for (int i = 0; i < 4; i++)
            #pragma unroll
            for (int j = 0; j < 4; j++) {
                int b = tm + i, n = n0 + tn + j;
                C[(size_t)b * G4H + n] = acc[i][j] + add[(size_t)b * G4H + n];
            }
        gsync(NBE);
        // cell update: 2*64*256 elems over 32*256 threads
        for (int g = blk * 256 + tid; g < 2 * BB * HH; g += NBE * 256) {
            int d2 = g >> 14;
            int b = (g >> 8) & 63;
            int j = g & 255;
            const float* gate = g_egate + (size_t)d2 * BB * G4H + (size_t)b * G4H;
            float gi = gate[j], gf = gate[HH + j], gg = gate[2 * HH + j], go = gate[3 * HH + j];
            int ci = d2 * BB * HH + b * HH + j;
            float c = g_cenc[ci];
            c = sigf(gf) * c + sigf(gi) * tanhf(gg);
            float hn = sigf(go) * tanhf(c);
            g_cenc[ci] = c;
            g_henc[ci] = hn;
            int s0 = d2 ? (SS - 1 - t) : t;
            g_h[((size_t)s0 * BB + b) * DHH + d2 * HH + j] = hn;
        }
        gsync(NBE);
    }
}

// ---------------- persistent decoder: levels [l0,l1), 128 steps each ----------------
__global__ void __launch_bounds__(256, 1) dec_persist(int l0, int l1) {
    __shared__ __align__(16) float hd_s[DHH];
    __shared__ float sc[SS];
    __shared__ float red[128];
    int blk = blockIdx.x, tid = threadIdx.x;
    int tm = (tid >> 4) << 2, tn = (tid & 15) << 2;
    for (int lvl = l0; lvl < l1; lvl++) {
        const float* pre = (lvl == 0) ? g_pre0 : g_pre1;
        const float* ohc = g_ohc + lvl * GD;
        for (int t = 0; t < SS; t++) {
            // ---- phase A: blocks 0-63 attention(batch b); blocks 64-127 hd-part GEMM ----
            if (blk < 64) {
                int b = blk;
                for (int i = tid; i < DHH; i += 256) hd_s[i] = g_hd[b * DHH + i];
                __syncthreads();
                int warp = tid >> 5, lane = tid & 31;
                for (int s0 = warp; s0 < SS; s0 += 8) {
                    const float4* w4 = (const float4*)(g_wh + ((size_t)s0 * BB + b) * DHH);
                    const float4* h4 = (const float4*)hd_s;
                    float sum = 0.f;
                    #pragma unroll
                    for (int q = 0; q < 4; q++) {
                        float4 a = w4[lane * 4 + q];
                        float4 c = h4[lane * 4 + q];
                        sum += a.x * c.x + a.y * c.y + a.z * c.z + a.w * c.w;
                    }
                    #pragma unroll
                    for (int off = 16; off; off >>= 1) sum += __shfl_xor_sync(0xffffffffu, sum, off);
                    if (lane == 0) sc[s0] = sum;
                }
                __syncthreads();
                if (tid < 128) red[tid] = sc[tid];
                __syncthreads();
                for (int off = 64; off; off >>= 1) {
                    if (tid < off) red[tid] = fmaxf(red[tid], red[tid + off]);
                    __syncthreads();
                }
                float mx = red[0];
                __syncthreads();
                if (tid < 128) { float e = expf(sc[tid] - mx); sc[tid] = e; red[tid] = e; }
                __syncthreads();
                for (int off = 64; off; off >>= 1) {
                    if (tid < off) red[tid] += red[tid + off];
                    __syncthreads();
                }
                float inv = 1.f / red[0];
                __syncthreads();
                for (int d = tid; d < DHH; d += 256) {
                    float acc = 0.f;
                    #pragma unroll 4
                    for (int s0 = 0; s0 < SS; s0++)
                        acc += sc[s0] * g_h[((size_t)s0 * BB + b) * DHH + d];
                    g_ctx[b * DHH + d] = acc * inv;
                }
            } else {
                int b2 = blk - 64;                 // 0..63
                int r = b2 >> 5;                   // 0/1: hd k-split
                int n0 = (b2 & 31) * 64;
                float acc[4][4] = {};
                gemm64_core(g_hd + r * 256, DHH, g_Wcat + 512 + r * 256, 1024, 256, 0, n0, acc);
                float* C = g_gpart + (size_t)(4 + r) * BB * GD;
                #pragma unroll
                for (int i = 0; i < 4; i++)
                    #pragma unroll
                    for (int j = 0; j < 4; j++)
                        C[(size_t)(tm + i) * GD + n0 + tn + j] = acc[i][j];
            }
            gsync(NBD);
            // ---- phase B: ctx-part GEMM, all 128 blocks, k-split 4 ----
            {
                int r = blk >> 5;                  // 0..3
                int n0 = (blk & 31) * 64;
                float acc[4][4] = {};
                gemm64_core(g_ctx + r * 128, DHH, g_Wcat + r * 128, 1024, 128, 0, n0, acc);
                float* C = g_gpart + (size_t)r * BB * GD;
                #pragma unroll
                for (int i = 0; i < 4; i++)
                    #pragma unroll
                    for (int j = 0; j < 4; j++)
                        C[(size_t)(tm + i) * GD + n0 + tn + j] = acc[i][j];
            }
            gsync(NBD);
            // ---- phase C: cell update, 32768 threads = 64*512 elems ----
            {
                int g = blk * 256 + tid;
                int b = g >> 9, j = g & 511;
                const float* prow = pre + ((size_t)t * BB + b) * GD;
                float g4[4];
                #pragma unroll
                for (int q = 0; q < 4; q++) {
                    int n = q * DHH + j;
                    float v = prow[n] + ohc[n];
                    #pragma unroll
                    for (int r = 0; r < 6; r++) v += g_gpart[((size_t)r * BB + b) * GD + n];
                    g4[q] = v;
                }
                int ci = b * DHH + j;
                float c = g_cd[ci];
                c = sigf(g4[1]) * c + sigf(g4[0]) * tanhf(g4[2]);
                float hn = sigf(g4[3]) * tanhf(c);
                g_cd[ci] = c;
                g_hd[ci] = hn;
                g_dout[(((size_t)lvl * SS + t) * BB + b) * DHH + j] = hn;
            }
            gsync(NBD);
        }
    }
}

// ---------------- output projection ----------------
__global__ void out_proj(const float* __restrict__ W2, const float* __restrict__ b2,
                         float* __restrict__ out) {
    int m = blockIdx.x;
    int lane = threadIdx.x;
    const float* drow = g_dout + (size_t)m * DHH;
    float acc[CC] = {};
    for (int k = lane; k < DHH; k += 32) {
        float d = drow[k];
        #pragma unroll
        for (int c = 0; c < CC; c++) acc[c] += d * W2[c * DHH + k];
    }
    #pragma unroll
    for (int c = 0; c < CC; c++) {
        float v = acc[c];
        #pragma unroll
        for (int off = 16; off; off >>= 1) v += __shfl_xor_sync(0xffffffffu, v, off);
        if (lane == 0) out[(size_t)m * CC + c] = v + b2[c];
    }
}

// ---------------- host ----------------
static void* symaddr(const void* sym) { void* p = nullptr; cudaGetSymbolAddress(&p, sym); return p; }

extern "C" void kernel_launch(void* const* d_in, const int* in_sizes, int n_in,
                              void* d_out, int out_size) {
    const int*   seqs  = (const int*)d_in[0];
    const float* emb   = (const float*)d_in[2];
    const float* Wih_f = (const float*)d_in[3];
    const float* Whh_f = (const float*)d_in[4];
    const float* bih_f = (const float*)d_in[5];
    const float* bhh_f = (const float*)d_in[6];
    const float* Wih_b = (const float*)d_in[7];
    const float* Whh_b = (const float*)d_in[8];
    const float* bih_b = (const float*)d_in[9];
    const float* bhh_b = (const float*)d_in[10];
    const float* Wl    = (const float*)d_in[11];
    const float* Wih_d = (const float*)d_in[12];
    const float* Whh_d = (const float*)d_in[13];
    const float* bih_d = (const float*)d_in[14];
    const float* bhh_d = (const float*)d_in[15];
    const float* W2    = (const float*)d_in[16];
    const float* b2    = (const float*)d_in[17];
    float* out = (float*)d_out;

    float* px    = (float*)symaddr(g_x);
    float* pgxf  = (float*)symaddr(g_gxf);
    float* pgxb  = (float*)symaddr(g_gxb);
    float* ph    = (float*)symaddr(g_h);
    float* phx   = (float*)symaddr(g_hx);
    float* pwh   = (float*)symaddr(g_wh);
    float* ppreS = (float*)symaddr(g_preS);
    float* ppre0 = (float*)symaddr(g_pre0);
    float* ppre1 = (float*)symaddr(g_pre1);
    float* pdout = (float*)symaddr(g_dout);
    float* pbf   = (float*)symaddr(g_bf);
    float* pbb   = (float*)symaddr(g_bb);
    float* pbd   = (float*)symaddr(g_bd);

    // prep
    k_bias_pack<<<8, 256>>>(bih_f, bhh_f, bih_b, bhh_b, bih_d, bhh_d);
    k_wcat<<<(GD * 1024 + LMAXX * GD + 255) / 256, 256>>>(Wih_d, Whh_d);
    k_zero<<<128, 256>>>();
    k_embed<<<SS * BB, 128>>>(seqs, emb);

    // encoder input GEMMs
    gemm_nt<<<dim3(SS * BB / 64, G4H / 64), 256>>>(px, EE, Wih_f, EE, pgxf, G4H, EE, nullptr, pbf);
    gemm_nt<<<dim3(SS * BB / 64, G4H / 64), 256>>>(px, EE, Wih_b, EE, pgxb, G4H, EE, nullptr, pbb);

    // persistent encoder recurrence
    enc_persist<<<NBE, 256>>>(Whh_f, Whh_b);

    // attention precompute wh = h @ Wl^T
    gemm_nt<<<dim3(SS * BB / 64, DHH / 64), 256>>>(ph, DHH, Wl, DHH, pwh, DHH, DHH, nullptr, nullptr);

    // decoder precomputes
    k_hx<<<SS * BB * 1024 / 256, 256>>>();
    gemm_nt<<<dim3(SS * BB / 64, GD / 64), 256>>>(phx, 1024, Wih_d + 512, LDWD, ppreS, GD, 1024, nullptr, pbd);
    gemm_nt<<<dim3(SS * BB / 64, GD / 64), 256>>>(ph, DHH, Wih_d + 1536, LDWD, ppre0, GD, DHH, ppreS, nullptr);

    // decoder level 0 (persistent)
    dec_persist<<<NBD, 256>>>(0, 1);
    // prev_s for levels 1-3 = level-0 outputs
    gemm_nt<<<dim3(SS * BB / 64, GD / 64), 256>>>(pdout, DHH, Wih_d + 1536, LDWD, ppre1, GD, DHH, ppreS, nullptr);
    // decoder levels 1-3 (persistent)
    dec_persist<<<NBD, 256>>>(1, 4);

    // logits
    out_proj<<<LMAXX * SS * BB, 32>>>(W2, b2, out);
}